// round 4
// baseline (speedup 1.0000x reference)
#include <cuda_runtime.h>
#include <cuda_bf16.h>
#include <cuda_fp16.h>
#include <math.h>
#include <stdint.h>

#define N     8192
#define D     128
#define TWON  16384

#define DIAG_EXP2  7.38905609893065f     // exp(2): diagonal of sim matrix
// exp2 arg scale: sim_arg_log2 = 2*dot/ln2 = dot_int * 2/(ln2*127^2)
#define KSCALE     1.7889462e-4f

// -------- persistent device scratch --------
__device__ int8_t g_Hq[TWON * D];   // normalized rows quantized to int8 (x127)
__device__ float  g_pos[N];
__device__ float  g_rowsum[TWON];

// ============================================================
// helpers (baseline PTX only: sm_80-class instructions)
// ============================================================
__device__ __forceinline__ uint32_t smem_u32(const void* p) {
    uint32_t a;
    asm("{ .reg .u64 t; cvta.to.shared.u64 t, %1; cvt.u32.u64 %0, t; }" : "=r"(a) : "l"(p));
    return a;
}
__device__ __forceinline__ void cp_async16(uint32_t saddr, const void* gaddr) {
    asm volatile("cp.async.cg.shared.global [%0], [%1], 16;" :: "r"(saddr), "l"(gaddr) : "memory");
}
#define CP_COMMIT() asm volatile("cp.async.commit_group;" ::: "memory")
#define CP_WAIT0()  asm volatile("cp.async.wait_group 0;" ::: "memory")

__device__ __forceinline__ void ldmatrix_x4(uint32_t& r0, uint32_t& r1, uint32_t& r2,
                                            uint32_t& r3, uint32_t addr) {
    asm volatile("ldmatrix.sync.aligned.m8n8.x4.shared.b16 {%0,%1,%2,%3}, [%4];"
                 : "=r"(r0), "=r"(r1), "=r"(r2), "=r"(r3) : "r"(addr));
}
__device__ __forceinline__ void mma_s8(int* c, const uint32_t* a, uint32_t b0, uint32_t b1) {
    asm volatile("mma.sync.aligned.m16n8k32.row.col.s32.s8.s8.s32 "
                 "{%0,%1,%2,%3}, {%4,%5,%6,%7}, {%8,%9}, {%0,%1,%2,%3};"
                 : "+r"(c[0]), "+r"(c[1]), "+r"(c[2]), "+r"(c[3])
                 : "r"(a[0]), "r"(a[1]), "r"(a[2]), "r"(a[3]), "r"(b0), "r"(b1));
}
// pack two f32 -> f16x2, exp2 both halves, accumulate
__device__ __forceinline__ uint32_t f16x2_pack(float lo, float hi) {
    uint32_t r;
    asm("cvt.rn.f16x2.f32 %0, %1, %2;" : "=r"(r) : "f"(hi), "f"(lo));
    return r;
}
__device__ __forceinline__ uint32_t ex2_f16x2(uint32_t x) {
    uint32_t y;
    asm("ex2.approx.f16x2 %0, %1;" : "=r"(y) : "r"(x));
    return y;
}
__device__ __forceinline__ uint32_t hadd2(uint32_t a, uint32_t b) {
    uint32_t r;
    asm("add.rn.f16x2 %0, %1, %2;" : "=r"(r) : "r"(a), "r"(b));
    return r;
}

// ============================================================
// Kernel A: normalize + quantize to int8 (x127), positive-pair dot
// ============================================================
__global__ void nt_norm_kernel(const float* __restrict__ h1,
                               const float* __restrict__ h2) {
    int warp = (blockIdx.x * blockDim.x + threadIdx.x) >> 5;
    int lane = threadIdx.x & 31;
    if (warp >= N) return;

    float4 a = ((const float4*)(h1 + (size_t)warp * D))[lane];
    float4 b = ((const float4*)(h2 + (size_t)warp * D))[lane];

    float sa = a.x*a.x + a.y*a.y + a.z*a.z + a.w*a.w;
    float sb = b.x*b.x + b.y*b.y + b.z*b.z + b.w*b.w;
    float sd = a.x*b.x + a.y*b.y + a.z*b.z + a.w*b.w;
    #pragma unroll
    for (int o = 16; o; o >>= 1) {
        sa += __shfl_xor_sync(0xffffffffu, sa, o);
        sb += __shfl_xor_sync(0xffffffffu, sb, o);
        sd += __shfl_xor_sync(0xffffffffu, sd, o);
    }
    float ra = 1.0f / fmaxf(sqrtf(sa), 1e-12f);
    float rb = 1.0f / fmaxf(sqrtf(sb), 1e-12f);
    if (lane == 0) g_pos[warp] = sd * ra * rb;

    float fa = ra * 127.0f, fb = rb * 127.0f;
    int qa0 = __float2int_rn(a.x*fa), qa1 = __float2int_rn(a.y*fa);
    int qa2 = __float2int_rn(a.z*fa), qa3 = __float2int_rn(a.w*fa);
    int qb0 = __float2int_rn(b.x*fb), qb1 = __float2int_rn(b.y*fb);
    int qb2 = __float2int_rn(b.z*fb), qb3 = __float2int_rn(b.w*fb);
    uint32_t pa = (qa0 & 0xFF) | ((qa1 & 0xFF) << 8) | ((qa2 & 0xFF) << 16) | ((uint32_t)(qa3 & 0xFF) << 24);
    uint32_t pb = (qb0 & 0xFF) | ((qb1 & 0xFF) << 8) | ((qb2 & 0xFF) << 16) | ((uint32_t)(qb3 & 0xFF) << 24);
    ((uint32_t*)(g_Hq + (size_t)warp * D))[lane]       = pa;
    ((uint32_t*)(g_Hq + (size_t)(warp + N) * D))[lane] = pb;
}

// ============================================================
// Kernel B: int8 IMMA GEMM + exp2(f16x2) + row-sum
//   CTA: 128 i-rows x 128 j-cols per tile, 128 j-tiles.
//   Warps: 4 m-groups x 2 n-groups (warp tile 32x64).
//   A fragments persistent in registers; B double-buffered cp.async.
//   Rows padded to 144B -> conflict-free ldmatrix.
// ============================================================
#define ROWB     144                     // 128 int8 + 16 pad
#define A_OFF    0
#define A_BYTES  (128 * ROWB)            // 18432
#define B_OFF    A_BYTES
#define B_BYTES  (128 * ROWB)
#define RED_OFF  (B_OFF + 2 * B_BYTES)
#define SMEM_SZ  (RED_OFF + 2 * 128 * 4)

__device__ __forceinline__ void cp_tile(uint32_t sbase, const int8_t* src, int tid) {
    // 128 rows x 8 chunks of 16B
    #pragma unroll
    for (int c = tid; c < 1024; c += 256) {
        int r  = c >> 3;
        int kc = c & 7;
        cp_async16(sbase + r * ROWB + kc * 16, src + (size_t)r * D + kc * 16);
    }
}

__global__ void __launch_bounds__(256, 1) nt_gemm_imma() {
    extern __shared__ char smem[];
    uint32_t sb = smem_u32(smem);
    const int tid    = threadIdx.x;
    const int lane   = tid & 31;
    const int wid    = tid >> 5;
    const int warp_m = wid & 3;      // rows warp_m*32
    const int warp_n = wid >> 2;     // cols warp_n*64
    const int i0     = blockIdx.x * 128;

    // ---- prologue ----
    cp_tile(sb + A_OFF, g_Hq + (size_t)i0 * D, tid);
    cp_tile(sb + B_OFF, g_Hq, tid);
    CP_COMMIT();
    CP_WAIT0();
    __syncthreads();

    // ---- A fragments to registers: 4 k-steps x 2 m-atoms ----
    // x4 addr: lanes 0-7 rows 0-7 @k-chunk0, 8-15 rows 8-15 @chunk0,
    //          16-23 rows 0-7 @chunk+16B, 24-31 rows 8-15 @chunk+16B
    uint32_t afrag[4][2][4];
    {
        uint32_t abase = sb + A_OFF + (warp_m * 32 + (lane & 15)) * ROWB + (lane >> 4) * 16;
        #pragma unroll
        for (int kst = 0; kst < 4; ++kst)
            #pragma unroll
            for (int ma = 0; ma < 2; ++ma)
                ldmatrix_x4(afrag[kst][ma][0], afrag[kst][ma][1],
                            afrag[kst][ma][2], afrag[kst][ma][3],
                            abase + ma * 16 * ROWB + kst * 32);
    }

    float rs[4] = {0.f, 0.f, 0.f, 0.f};
    uint32_t bbase0 = sb + B_OFF + (warp_n * 64 + (lane & 15)) * ROWB + (lane >> 4) * 16;

    for (int t = 0; t < 128; ++t) {
        if (t + 1 < 128) {
            cp_tile(sb + B_OFF + ((t + 1) & 1) * B_BYTES,
                    g_Hq + (size_t)(t + 1) * 128 * D, tid);
            CP_COMMIT();
        }

        uint32_t bbase = bbase0 + (t & 1) * B_BYTES;
        int acc[2][8][4];
        #pragma unroll
        for (int ma = 0; ma < 2; ++ma)
            #pragma unroll
            for (int na = 0; na < 8; ++na)
                #pragma unroll
                for (int q = 0; q < 4; ++q) acc[ma][na][q] = 0;

        #pragma unroll
        for (int kst = 0; kst < 4; ++kst) {
            uint32_t b[8][2];
            #pragma unroll
            for (int pr = 0; pr < 4; ++pr) {
                uint32_t r0, r1, r2, r3;
                ldmatrix_x4(r0, r1, r2, r3, bbase + pr * 16 * ROWB + kst * 32);
                b[pr*2    ][0] = r0; b[pr*2    ][1] = r2;   // n-atom pr*2:   b0,b1
                b[pr*2 + 1][0] = r1; b[pr*2 + 1][1] = r3;   // n-atom pr*2+1: b0,b1
            }
            #pragma unroll
            for (int ma = 0; ma < 2; ++ma)
                #pragma unroll
                for (int na = 0; na < 8; ++na)
                    mma_s8(acc[ma][na], afrag[kst][ma], b[na][0], b[na][1]);
        }

        // ---- epilogue: exp2(KSCALE * acc) via packed f16x2 MUFU ----
        // acc[ma][na]: c0,c1 -> row (lane>>2)+ma*16+warp_m*32; c2,c3 -> +8
        uint32_t inner[2][2];
        inner[0][0] = inner[0][1] = inner[1][0] = inner[1][1] = 0;  // +0.0 x2 in f16x2
        #pragma unroll
        for (int ma = 0; ma < 2; ++ma) {
            #pragma unroll
            for (int na = 0; na < 8; ++na) {
                float f0 = (float)acc[ma][na][0] * KSCALE;
                float f1 = (float)acc[ma][na][1] * KSCALE;
                float f2 = (float)acc[ma][na][2] * KSCALE;
                float f3 = (float)acc[ma][na][3] * KSCALE;
                inner[ma][0] = hadd2(inner[ma][0], ex2_f16x2(f16x2_pack(f0, f1)));
                inner[ma][1] = hadd2(inner[ma][1], ex2_f16x2(f16x2_pack(f2, f3)));
            }
            __half2 h0 = *(__half2*)&inner[ma][0];
            __half2 h1 = *(__half2*)&inner[ma][1];
            float2 g0 = __half22float2(h0);
            float2 g1 = __half22float2(h1);
            rs[ma*2]     += g0.x + g0.y;
            rs[ma*2 + 1] += g1.x + g1.y;
        }

        CP_WAIT0();
        __syncthreads();
    }

    // ---- reduce across the 4 lanes of each quad (same rows, diff cols) ----
    #pragma unroll
    for (int i = 0; i < 4; ++i) {
        rs[i] += __shfl_xor_sync(0xffffffffu, rs[i], 1);
        rs[i] += __shfl_xor_sync(0xffffffffu, rs[i], 2);
    }
    float* red = (float*)(smem + RED_OFF);
    if ((lane & 3) == 0) {
        int r8 = lane >> 2;
        #pragma unroll
        for (int ma = 0; ma < 2; ++ma)
            #pragma unroll
            for (int p = 0; p < 2; ++p)
                red[warp_n * 128 + warp_m * 32 + ma * 16 + p * 8 + r8] = rs[ma*2 + p];
    }
    __syncthreads();
    if (tid < 128) g_rowsum[i0 + tid] = red[tid] + red[128 + tid];
}

// ============================================================
// Kernel C: loss = mean( log(rowsum - exp(2)) - 2*pos )
// ============================================================
__global__ void nt_loss_kernel(float* __restrict__ out) {
    __shared__ double sred[16];
    const int tid  = threadIdx.x;
    const int lane = tid & 31;
    const int wid  = tid >> 5;

    double s = 0.0;
    for (int i = tid; i < TWON; i += 512) {
        float denom = g_rowsum[i] - DIAG_EXP2;
        float term  = logf(denom) - 2.0f * g_pos[i & (N - 1)];
        s += (double)term;
    }
    #pragma unroll
    for (int o = 16; o; o >>= 1) s += __shfl_xor_sync(0xffffffffu, s, o);
    if (lane == 0) sred[wid] = s;
    __syncthreads();
    if (wid == 0) {
        double t = (lane < 16) ? sred[lane] : 0.0;
        #pragma unroll
        for (int o = 8; o; o >>= 1) t += __shfl_xor_sync(0xffffffffu, t, o);
        if (lane == 0) out[0] = (float)(t / (double)TWON);
    }
}

// ============================================================
extern "C" void kernel_launch(void* const* d_in, const int* in_sizes, int n_in,
                              void* d_out, int out_size) {
    const float* h1 = (const float*)d_in[0];
    const float* h2 = (const float*)d_in[1];
    float* out = (float*)d_out;

    nt_norm_kernel<<<N / 8, 256>>>(h1, h2);

    cudaFuncSetAttribute(nt_gemm_imma,
                         cudaFuncAttributeMaxDynamicSharedMemorySize, SMEM_SZ);
    nt_gemm_imma<<<TWON / 128, 256, SMEM_SZ>>>();

    nt_loss_kernel<<<1, 512>>>(out);
}

// round 5
// speedup vs baseline: 2.2145x; 2.2145x over previous
#include <cuda_runtime.h>
#include <cuda_bf16.h>
#include <cuda_fp16.h>
#include <math.h>
#include <stdint.h>

#define N     8192
#define D     128
#define TWON  16384

#define DIAG_EXP2  7.38905609893065f   // exp(2): diagonal of sim matrix
#define SQRT_SCALE 1.6986436f          // sqrt(2/ln2): acc = log2(exp arg)

// -------- persistent device scratch --------
__device__ __nv_bfloat16 g_Hb[TWON * D];   // normalized rows, pre-scaled
__device__ float g_pos[N];
__device__ float g_rowsum[TWON];

// ============================================================
// helpers (baseline PTX only)
// ============================================================
__device__ __forceinline__ uint32_t smem_u32(const void* p) {
    uint32_t a;
    asm("{ .reg .u64 t; cvta.to.shared.u64 t, %1; cvt.u32.u64 %0, t; }" : "=r"(a) : "l"(p));
    return a;
}
__device__ __forceinline__ void cp_async16(uint32_t saddr, const void* gaddr) {
    asm volatile("cp.async.cg.shared.global [%0], [%1], 16;" :: "r"(saddr), "l"(gaddr) : "memory");
}
#define CP_COMMIT() asm volatile("cp.async.commit_group;" ::: "memory")
#define CP_WAIT0()  asm volatile("cp.async.wait_group 0;" ::: "memory")

__device__ __forceinline__ void ldmatrix_x4(uint32_t& r0, uint32_t& r1, uint32_t& r2,
                                            uint32_t& r3, uint32_t addr) {
    asm volatile("ldmatrix.sync.aligned.m8n8.x4.shared.b16 {%0,%1,%2,%3}, [%4];"
                 : "=r"(r0), "=r"(r1), "=r"(r2), "=r"(r3) : "r"(addr));
}
__device__ __forceinline__ void mma_bf16(float* c, const uint32_t* a, uint32_t b0, uint32_t b1) {
    asm volatile("mma.sync.aligned.m16n8k16.row.col.f32.bf16.bf16.f32 "
                 "{%0,%1,%2,%3}, {%4,%5,%6,%7}, {%8,%9}, {%0,%1,%2,%3};"
                 : "+f"(c[0]), "+f"(c[1]), "+f"(c[2]), "+f"(c[3])
                 : "r"(a[0]), "r"(a[1]), "r"(a[2]), "r"(a[3]), "r"(b0), "r"(b1));
}
__device__ __forceinline__ uint32_t f16x2_pack(float lo, float hi) {
    uint32_t r;
    asm("cvt.rn.f16x2.f32 %0, %1, %2;" : "=r"(r) : "f"(hi), "f"(lo));
    return r;
}
__device__ __forceinline__ uint32_t ex2_f16x2(uint32_t x) {
    uint32_t y;
    asm("ex2.approx.f16x2 %0, %1;" : "=r"(y) : "r"(x));
    return y;
}
__device__ __forceinline__ uint32_t hadd2(uint32_t a, uint32_t b) {
    uint32_t r;
    asm("add.rn.f16x2 %0, %1, %2;" : "=r"(r) : "r"(a), "r"(b));
    return r;
}

// ============================================================
// Kernel A: normalize + pre-scale to bf16, positive-pair dot
// ============================================================
__global__ void nt_norm_kernel(const float* __restrict__ h1,
                               const float* __restrict__ h2) {
    int warp = (blockIdx.x * blockDim.x + threadIdx.x) >> 5;
    int lane = threadIdx.x & 31;
    if (warp >= N) return;

    float4 a = ((const float4*)(h1 + (size_t)warp * D))[lane];
    float4 b = ((const float4*)(h2 + (size_t)warp * D))[lane];

    float sa = a.x*a.x + a.y*a.y + a.z*a.z + a.w*a.w;
    float sb = b.x*b.x + b.y*b.y + b.z*b.z + b.w*b.w;
    float sd = a.x*b.x + a.y*b.y + a.z*b.z + a.w*b.w;
    #pragma unroll
    for (int o = 16; o; o >>= 1) {
        sa += __shfl_xor_sync(0xffffffffu, sa, o);
        sb += __shfl_xor_sync(0xffffffffu, sb, o);
        sd += __shfl_xor_sync(0xffffffffu, sd, o);
    }
    float ra = 1.0f / fmaxf(sqrtf(sa), 1e-12f);
    float rb = 1.0f / fmaxf(sqrtf(sb), 1e-12f);
    if (lane == 0) g_pos[warp] = sd * ra * rb;

    float fa = ra * SQRT_SCALE, fb = rb * SQRT_SCALE;
    union { __nv_bfloat162 b2[2]; uint2 u; } pa, pb;
    pa.b2[0] = __floats2bfloat162_rn(a.x*fa, a.y*fa);
    pa.b2[1] = __floats2bfloat162_rn(a.z*fa, a.w*fa);
    pb.b2[0] = __floats2bfloat162_rn(b.x*fb, b.y*fb);
    pb.b2[1] = __floats2bfloat162_rn(b.z*fb, b.w*fb);
    ((uint2*)(g_Hb + (size_t)warp * D))[lane]       = pa.u;
    ((uint2*)(g_Hb + (size_t)(warp + N) * D))[lane] = pb.u;
}

// ============================================================
// Kernel B: bf16 mma.sync GEMM + packed exp2 + row-sum
//   CTA: 128 i x 128 j tile, 512 threads = 16 warps (8 m x 2 n),
//   warp tile 16x64. 4 warps/SMSP -> cross-warp pipe overlap.
//   A fragments persistent in registers; B double-buffered cp.async.
// ============================================================
#define PADROW   136                    // bf16 elems per smem row
#define ROWB     (PADROW * 2)           // 272 bytes
#define A_OFF    0
#define A_BYTES  (128 * ROWB)
#define B_OFF    A_BYTES
#define B_BYTES  (128 * ROWB)
#define RED_OFF  (B_OFF + 2 * B_BYTES)
#define SMEM_SZ  (RED_OFF + 2 * 128 * 4)
#define NT       512

__device__ __forceinline__ void cp_tile(uint32_t sbase, const __nv_bfloat16* src, int tid) {
    // 128 rows x 16 chunks of 16B
    #pragma unroll
    for (int c = tid; c < 2048; c += NT) {
        int r  = c >> 4;
        int kc = c & 15;
        cp_async16(sbase + r * ROWB + kc * 16, src + (size_t)r * D + kc * 8);
    }
}

__global__ void __launch_bounds__(NT, 1) nt_gemm_mma() {
    extern __shared__ char smem[];
    uint32_t sb = smem_u32(smem);
    const int tid    = threadIdx.x;
    const int lane   = tid & 31;
    const int wid    = tid >> 5;
    const int warp_m = wid & 7;      // rows warp_m*16
    const int warp_n = wid >> 3;     // cols warp_n*64
    const int i0     = blockIdx.x * 128;

    // ---- prologue: A tile + first B tile ----
    cp_tile(sb + A_OFF, g_Hb + (size_t)i0 * D, tid);
    cp_tile(sb + B_OFF, g_Hb, tid);
    CP_COMMIT();
    CP_WAIT0();
    __syncthreads();

    // ---- A fragments to registers: 8 k-steps x 4 regs (16 rows) ----
    uint32_t afrag[8][4];
    {
        uint32_t abase = sb + A_OFF + (warp_m * 16 + (lane & 15)) * ROWB + (lane >> 4) * 16;
        #pragma unroll
        for (int kst = 0; kst < 8; ++kst)
            ldmatrix_x4(afrag[kst][0], afrag[kst][1], afrag[kst][2], afrag[kst][3],
                        abase + kst * 32);
    }

    float rs0 = 0.f, rs1 = 0.f;
    uint32_t bbase0 = sb + B_OFF + (warp_n * 64 + (lane & 15)) * ROWB + (lane >> 4) * 16;

    for (int t = 0; t < 128; ++t) {
        if (t + 1 < 128) {
            cp_tile(sb + B_OFF + ((t + 1) & 1) * B_BYTES,
                    g_Hb + (size_t)(t + 1) * 128 * D, tid);
            CP_COMMIT();
        }

        uint32_t bbase = bbase0 + (t & 1) * B_BYTES;
        float acc[8][4];
        #pragma unroll
        for (int na = 0; na < 8; ++na)
            #pragma unroll
            for (int q = 0; q < 4; ++q) acc[na][q] = 0.f;

        #pragma unroll
        for (int kst = 0; kst < 8; ++kst) {
            uint32_t b[8][2];
            #pragma unroll
            for (int pr = 0; pr < 4; ++pr) {
                uint32_t r0, r1, r2, r3;
                ldmatrix_x4(r0, r1, r2, r3, bbase + pr * 16 * ROWB + kst * 32);
                b[pr*2    ][0] = r0; b[pr*2    ][1] = r2;
                b[pr*2 + 1][0] = r1; b[pr*2 + 1][1] = r3;
            }
            #pragma unroll
            for (int na = 0; na < 8; ++na)
                mma_bf16(acc[na], afrag[kst], b[na][0], b[na][1]);
        }

        // ---- epilogue: packed exp2, f16x2 inner sums (8 terms <= ~60) ----
        // acc[na]: c0,c1 -> row lane>>2 ; c2,c3 -> row (lane>>2)+8
        uint32_t in0 = 0, in1 = 0;
        #pragma unroll
        for (int na = 0; na < 8; ++na) {
            in0 = hadd2(in0, ex2_f16x2(f16x2_pack(acc[na][0], acc[na][1])));
            in1 = hadd2(in1, ex2_f16x2(f16x2_pack(acc[na][2], acc[na][3])));
        }
        {
            float2 g0 = __half22float2(*(__half2*)&in0);
            float2 g1 = __half22float2(*(__half2*)&in1);
            rs0 += g0.x + g0.y;
            rs1 += g1.x + g1.y;
        }

        CP_WAIT0();
        __syncthreads();
    }

    // ---- reduce across the 4 lanes of each quad (same row, diff cols) ----
    rs0 += __shfl_xor_sync(0xffffffffu, rs0, 1);
    rs0 += __shfl_xor_sync(0xffffffffu, rs0, 2);
    rs1 += __shfl_xor_sync(0xffffffffu, rs1, 1);
    rs1 += __shfl_xor_sync(0xffffffffu, rs1, 2);

    float* red = (float*)(smem + RED_OFF);
    if ((lane & 3) == 0) {
        int r8 = lane >> 2;
        red[warp_n * 128 + warp_m * 16 + r8]     = rs0;
        red[warp_n * 128 + warp_m * 16 + 8 + r8] = rs1;
    }
    __syncthreads();
    if (tid < 128) g_rowsum[i0 + tid] = red[tid] + red[128 + tid];
}

// ============================================================
// Kernel C: loss = mean( log(rowsum - exp(2)) - 2*pos )
// ============================================================
__global__ void nt_loss_kernel(float* __restrict__ out) {
    __shared__ double sred[16];
    const int tid  = threadIdx.x;
    const int lane = tid & 31;
    const int wid  = tid >> 5;

    double s = 0.0;
    for (int i = tid; i < TWON; i += 512) {
        float denom = g_rowsum[i] - DIAG_EXP2;
        float term  = logf(denom) - 2.0f * g_pos[i & (N - 1)];
        s += (double)term;
    }
    #pragma unroll
    for (int o = 16; o; o >>= 1) s += __shfl_xor_sync(0xffffffffu, s, o);
    if (lane == 0) sred[wid] = s;
    __syncthreads();
    if (wid == 0) {
        double t = (lane < 16) ? sred[lane] : 0.0;
        #pragma unroll
        for (int o = 8; o; o >>= 1) t += __shfl_xor_sync(0xffffffffu, t, o);
        if (lane == 0) out[0] = (float)(t / (double)TWON);
    }
}

// ============================================================
extern "C" void kernel_launch(void* const* d_in, const int* in_sizes, int n_in,
                              void* d_out, int out_size) {
    const float* h1 = (const float*)d_in[0];
    const float* h2 = (const float*)d_in[1];
    float* out = (float*)d_out;

    nt_norm_kernel<<<N / 8, 256>>>(h1, h2);

    cudaFuncSetAttribute(nt_gemm_mma,
                         cudaFuncAttributeMaxDynamicSharedMemorySize, SMEM_SZ);
    nt_gemm_mma<<<TWON / 128, NT, SMEM_SZ>>>();

    nt_loss_kernel<<<1, 512>>>(out);
}

// round 6
// speedup vs baseline: 2.7896x; 1.2597x over previous
#include <cuda_runtime.h>
#include <cuda_bf16.h>
#include <cuda_fp16.h>
#include <math.h>
#include <stdint.h>

#define N     8192
#define D     128
#define TWON  16384
#define NTILE 128              // 128-row blocks
#define NPAIR 8256             // NTILE*(NTILE+1)/2

#define DIAG_EXP2  7.38905609893065f
#define SQRT_SCALE 1.6986436f  // sqrt(2/ln2): acc = log2(exp arg)

// -------- persistent device scratch --------
__device__ __nv_bfloat16 g_Hb[TWON * D];
__device__ float g_pos[N];
__device__ float g_rowsum[TWON];
__device__ int   g_ctr;

// ============================================================
// helpers
// ============================================================
__device__ __forceinline__ uint32_t smem_u32(const void* p) {
    uint32_t a;
    asm("{ .reg .u64 t; cvta.to.shared.u64 t, %1; cvt.u32.u64 %0, t; }" : "=r"(a) : "l"(p));
    return a;
}
__device__ __forceinline__ void cp_async16(uint32_t saddr, const void* gaddr) {
    asm volatile("cp.async.cg.shared.global [%0], [%1], 16;" :: "r"(saddr), "l"(gaddr) : "memory");
}
#define CP_COMMIT() asm volatile("cp.async.commit_group;" ::: "memory")
#define CP_WAIT1()  asm volatile("cp.async.wait_group 1;" ::: "memory")

__device__ __forceinline__ void ldmatrix_x4(uint32_t& r0, uint32_t& r1, uint32_t& r2,
                                            uint32_t& r3, uint32_t addr) {
    asm volatile("ldmatrix.sync.aligned.m8n8.x4.shared.b16 {%0,%1,%2,%3}, [%4];"
                 : "=r"(r0), "=r"(r1), "=r"(r2), "=r"(r3) : "r"(addr));
}
__device__ __forceinline__ void mma_bf16(float* c, const uint32_t* a, uint32_t b0, uint32_t b1) {
    asm volatile("mma.sync.aligned.m16n8k16.row.col.f32.bf16.bf16.f32 "
                 "{%0,%1,%2,%3}, {%4,%5,%6,%7}, {%8,%9}, {%0,%1,%2,%3};"
                 : "+f"(c[0]), "+f"(c[1]), "+f"(c[2]), "+f"(c[3])
                 : "r"(a[0]), "r"(a[1]), "r"(a[2]), "r"(a[3]), "r"(b0), "r"(b1));
}
__device__ __forceinline__ uint32_t f16x2_pack(float lo, float hi) {
    uint32_t r;  // PTX cvt.rn.f16x2.f32 d,a,b : high=a, low=b
    asm("cvt.rn.f16x2.f32 %0, %1, %2;" : "=r"(r) : "f"(hi), "f"(lo));
    return r;
}
__device__ __forceinline__ uint32_t ex2_f16x2(uint32_t x) {
    uint32_t y;
    asm("ex2.approx.f16x2 %0, %1;" : "=r"(y) : "r"(x));
    return y;
}
__device__ __forceinline__ uint32_t hadd2(uint32_t a, uint32_t b) {
    uint32_t r;
    asm("add.rn.f16x2 %0, %1, %2;" : "=r"(r) : "r"(a), "r"(b));
    return r;
}
// t in [0, NPAIR) -> (I,J), I<=J, row-major over upper triangle
__device__ __forceinline__ void decode_pair(int t, int& I, int& J) {
    int r = NPAIR - t;                       // remaining incl. this one
    float nf = (sqrtf(8.0f * (float)r + 1.0f) - 1.0f) * 0.5f;
    int n = (int)ceilf(nf);
    while (n * (n + 1) / 2 < r) n++;
    while (n >= 1 && (n - 1) * n / 2 >= r) n--;
    I = NTILE - n;
    int S = NPAIR - n * (n + 1) / 2;         // pairs before row I
    J = I + (t - S);
}

// ============================================================
// Kernel A: normalize + pre-scale to bf16; also zero rowsum/ctr
// ============================================================
__global__ void nt_norm_kernel(const float* __restrict__ h1,
                               const float* __restrict__ h2) {
    int gid = blockIdx.x * blockDim.x + threadIdx.x;
    if (gid < TWON) g_rowsum[gid] = 0.0f;
    if (gid == 0)   g_ctr = 0;

    int warp = gid >> 5;
    int lane = threadIdx.x & 31;
    if (warp >= N) return;

    float4 a = ((const float4*)(h1 + (size_t)warp * D))[lane];
    float4 b = ((const float4*)(h2 + (size_t)warp * D))[lane];

    float sa = a.x*a.x + a.y*a.y + a.z*a.z + a.w*a.w;
    float sb = b.x*b.x + b.y*b.y + b.z*b.z + b.w*b.w;
    float sd = a.x*b.x + a.y*b.y + a.z*b.z + a.w*b.w;
    #pragma unroll
    for (int o = 16; o; o >>= 1) {
        sa += __shfl_xor_sync(0xffffffffu, sa, o);
        sb += __shfl_xor_sync(0xffffffffu, sb, o);
        sd += __shfl_xor_sync(0xffffffffu, sd, o);
    }
    float ra = 1.0f / fmaxf(sqrtf(sa), 1e-12f);
    float rb = 1.0f / fmaxf(sqrtf(sb), 1e-12f);
    if (lane == 0) g_pos[warp] = sd * ra * rb;

    float fa = ra * SQRT_SCALE, fb = rb * SQRT_SCALE;
    union { __nv_bfloat162 b2[2]; uint2 u; } pa, pb;
    pa.b2[0] = __floats2bfloat162_rn(a.x*fa, a.y*fa);
    pa.b2[1] = __floats2bfloat162_rn(a.z*fa, a.w*fa);
    pb.b2[0] = __floats2bfloat162_rn(b.x*fb, b.y*fb);
    pb.b2[1] = __floats2bfloat162_rn(b.z*fb, b.w*fb);
    ((uint2*)(g_Hb + (size_t)warp * D))[lane]       = pa.u;
    ((uint2*)(g_Hb + (size_t)(warp + N) * D))[lane] = pb.u;
}

// ============================================================
// Kernel B: symmetric-pair persistent GEMM + exp2 + row/col sums
//   256 threads = 8 warps (4 m x 2 n), warp tile 32x64.
//   Dynamic work counter over 8256 (I<=J) tile pairs.
//   A+B double-buffered (prefetch next pair while computing).
// ============================================================
#define PADROW   136
#define ROWB     (PADROW * 2)           // 272B
#define T_BYTES  (128 * ROWB)           // one 128-row tile = 34816B
#define BUF_BYTES (2 * T_BYTES)         // A + B
#define SMEM_SZ  (2 * BUF_BYTES)        // double buffered = 139264
#define NT       256

__device__ __forceinline__ void cp_pair(uint32_t sbase, int I, int J, int tid) {
    const __nv_bfloat16* Asrc = g_Hb + (size_t)I * 128 * D;
    const __nv_bfloat16* Bsrc = g_Hb + (size_t)J * 128 * D;
    #pragma unroll
    for (int c = tid; c < 2048; c += NT) {
        int r  = c >> 4;
        int kc = c & 15;
        cp_async16(sbase + r * ROWB + kc * 16, Asrc + (size_t)r * D + kc * 8);
        cp_async16(sbase + T_BYTES + r * ROWB + kc * 16, Bsrc + (size_t)r * D + kc * 8);
    }
}

__global__ void __launch_bounds__(NT, 1) nt_gemm_sym() {
    extern __shared__ char smem[];
    __shared__ int s_t;
    uint32_t sb = smem_u32(smem);
    const int tid    = threadIdx.x;
    const int lane   = tid & 31;
    const int wid    = tid >> 5;
    const int warp_m = wid & 3;      // rows warp_m*32
    const int warp_n = wid >> 2;     // cols warp_n*64

    // ---- get first tile, start its load ----
    if (tid == 0) s_t = atomicAdd(&g_ctr, 1);
    __syncthreads();
    int t = s_t, I = 0, J = 0;
    if (t < NPAIR) decode_pair(t, I, J);
    if (t < NPAIR) cp_pair(sb, I, J, tid);
    CP_COMMIT();

    // ---- get second tile index ----
    if (tid == 0) s_t = atomicAdd(&g_ctr, 1);
    __syncthreads();
    int tn = s_t, In = 0, Jn = 0;
    if (tn < NPAIR) decode_pair(tn, In, Jn);

    int p = 0;
    while (t < NPAIR) {
        // prefetch next pair into other buffer
        if (tn < NPAIR) cp_pair(sb + (p ^ 1) * BUF_BYTES, In, Jn, tid);
        CP_COMMIT();

        CP_WAIT1();          // current buffer's group complete
        __syncthreads();

        uint32_t abuf = sb + p * BUF_BYTES;
        uint32_t bbuf = abuf + T_BYTES;

        // ---- A fragments: 8 kst x 2 ma x 4 regs ----
        uint32_t afrag[8][2][4];
        {
            uint32_t abase = abuf + (warp_m * 32 + (lane & 15)) * ROWB + (lane >> 4) * 16;
            #pragma unroll
            for (int kst = 0; kst < 8; ++kst)
                #pragma unroll
                for (int ma = 0; ma < 2; ++ma)
                    ldmatrix_x4(afrag[kst][ma][0], afrag[kst][ma][1],
                                afrag[kst][ma][2], afrag[kst][ma][3],
                                abase + ma * 16 * ROWB + kst * 32);
        }

        float acc[2][8][4];
        #pragma unroll
        for (int ma = 0; ma < 2; ++ma)
            #pragma unroll
            for (int na = 0; na < 8; ++na)
                #pragma unroll
                for (int q = 0; q < 4; ++q) acc[ma][na][q] = 0.f;

        uint32_t bbase = bbuf + (warp_n * 64 + (lane & 15)) * ROWB + (lane >> 4) * 16;
        #pragma unroll
        for (int kst = 0; kst < 8; ++kst) {
            uint32_t b[8][2];
            #pragma unroll
            for (int pr = 0; pr < 4; ++pr) {
                uint32_t r0, r1, r2, r3;
                ldmatrix_x4(r0, r1, r2, r3, bbase + pr * 16 * ROWB + kst * 32);
                b[pr*2    ][0] = r0; b[pr*2    ][1] = r2;
                b[pr*2 + 1][0] = r1; b[pr*2 + 1][1] = r3;
            }
            #pragma unroll
            for (int ma = 0; ma < 2; ++ma)
                #pragma unroll
                for (int na = 0; na < 8; ++na)
                    mma_bf16(acc[ma][na], afrag[kst][ma], b[na][0], b[na][1]);
        }

        // ---- epilogue: exp2 once; rowsums (f32) + colsums (f16x2) ----
        // acc[ma][na]: c0,c1 -> row lane>>2 + ma*16 (+warp_m*32), cols 2*(lane&3)+{0,1} (+na*8+warp_n*64)
        //              c2,c3 -> row +8, same cols
        const bool diag = (I == J);
        float rs[4] = {0.f, 0.f, 0.f, 0.f};   // rows +0,+8,+16,+24
        uint32_t colacc[8];
        #pragma unroll
        for (int na = 0; na < 8; ++na) colacc[na] = 0;

        #pragma unroll
        for (int ma = 0; ma < 2; ++ma) {
            #pragma unroll
            for (int na = 0; na < 8; ++na) {
                uint32_t e01 = ex2_f16x2(f16x2_pack(acc[ma][na][0], acc[ma][na][1]));
                uint32_t e23 = ex2_f16x2(f16x2_pack(acc[ma][na][2], acc[ma][na][3]));
                float2 g0 = __half22float2(*(__half2*)&e01);
                float2 g1 = __half22float2(*(__half2*)&e23);
                rs[ma*2]     += g0.x + g0.y;
                rs[ma*2 + 1] += g1.x + g1.y;
                colacc[na] = hadd2(colacc[na], hadd2(e01, e23));
            }
        }

        // rowsum: reduce over 4 quad lanes (different col groups)
        #pragma unroll
        for (int i = 0; i < 4; ++i) {
            rs[i] += __shfl_xor_sync(0xffffffffu, rs[i], 1);
            rs[i] += __shfl_xor_sync(0xffffffffu, rs[i], 2);
        }
        if ((lane & 3) == 0) {
            int r8 = lane >> 2;
            #pragma unroll
            for (int i = 0; i < 4; ++i)
                atomicAdd(&g_rowsum[I * 128 + warp_m * 32 + i * 8 + r8], rs[i]);
        }

        // colsum: reduce over 8 row-group lanes (xor 4, 8, 16), flush lanes 0-3
        if (!diag) {
            #pragma unroll
            for (int na = 0; na < 8; ++na) {
                uint32_t v = colacc[na];
                v = hadd2(v, __shfl_xor_sync(0xffffffffu, v, 4));
                v = hadd2(v, __shfl_xor_sync(0xffffffffu, v, 8));
                v = hadd2(v, __shfl_xor_sync(0xffffffffu, v, 16));
                if (lane < 4) {
                    float2 cs = __half22float2(*(__half2*)&v);
                    int col = J * 128 + warp_n * 64 + na * 8 + lane * 2;
                    atomicAdd(&g_rowsum[col],     cs.x);
                    atomicAdd(&g_rowsum[col + 1], cs.y);
                }
            }
        }

        // ---- advance ----
        if (tid == 0) s_t = atomicAdd(&g_ctr, 1);
        __syncthreads();          // buffer reuse + s_t visibility
        t = tn; I = In; J = Jn;
        tn = s_t;
        if (tn < NPAIR) decode_pair(tn, In, Jn);
        p ^= 1;
    }
}

// ============================================================
// Kernel C: loss = mean( log(rowsum - exp(2)) - 2*pos )
// ============================================================
__global__ void nt_loss_kernel(float* __restrict__ out) {
    __shared__ double sred[16];
    const int tid  = threadIdx.x;
    const int lane = tid & 31;
    const int wid  = tid >> 5;

    double s = 0.0;
    for (int i = tid; i < TWON; i += 512) {
        float denom = g_rowsum[i] - DIAG_EXP2;
        float term  = logf(denom) - 2.0f * g_pos[i & (N - 1)];
        s += (double)term;
    }
    #pragma unroll
    for (int o = 16; o; o >>= 1) s += __shfl_xor_sync(0xffffffffu, s, o);
    if (lane == 0) sred[wid] = s;
    __syncthreads();
    if (wid == 0) {
        double tt = (lane < 16) ? sred[lane] : 0.0;
        #pragma unroll
        for (int o = 8; o; o >>= 1) tt += __shfl_xor_sync(0xffffffffu, tt, o);
        if (lane == 0) out[0] = (float)(tt / (double)TWON);
    }
}

// ============================================================
extern "C" void kernel_launch(void* const* d_in, const int* in_sizes, int n_in,
                              void* d_out, int out_size) {
    const float* h1 = (const float*)d_in[0];
    const float* h2 = (const float*)d_in[1];
    float* out = (float*)d_out;

    nt_norm_kernel<<<1024, 256>>>(h1, h2);

    cudaFuncSetAttribute(nt_gemm_sym,
                         cudaFuncAttributeMaxDynamicSharedMemorySize, SMEM_SZ);
    nt_gemm_sym<<<148, NT, SMEM_SZ>>>();

    nt_loss_kernel<<<1, 512>>>(out);
}

// round 7
// speedup vs baseline: 3.3738x; 1.2094x over previous
#include <cuda_runtime.h>
#include <cuda_bf16.h>
#include <cuda_fp16.h>
#include <math.h>
#include <stdint.h>

#define N     8192
#define D     128
#define TWON  16384
#define NTILE 128
#define NPAIR 8256             // NTILE*(NTILE+1)/2
#define CHUNK 8
#define NCHUNK (NPAIR / CHUNK) // 1032

#define DIAG_EXP2  7.38905609893065f
#define SQRT_SCALE 1.6986436f  // sqrt(2/ln2): acc = log2(exp arg)

// -------- persistent device scratch --------
__device__ __nv_bfloat16 g_Hb[TWON * D];
__device__ float g_pos[N];
__device__ float g_rowsum[TWON];
__device__ int   g_ctr;

// ============================================================
// helpers
// ============================================================
__device__ __forceinline__ uint32_t smem_u32(const void* p) {
    uint32_t a;
    asm("{ .reg .u64 t; cvta.to.shared.u64 t, %1; cvt.u32.u64 %0, t; }" : "=r"(a) : "l"(p));
    return a;
}
__device__ __forceinline__ void cp_async16(uint32_t saddr, const void* gaddr) {
    asm volatile("cp.async.cg.shared.global [%0], [%1], 16;" :: "r"(saddr), "l"(gaddr) : "memory");
}
#define CP_COMMIT() asm volatile("cp.async.commit_group;" ::: "memory")
#define CP_WAIT1()  asm volatile("cp.async.wait_group 1;" ::: "memory")

__device__ __forceinline__ void ldmatrix_x4(uint32_t& r0, uint32_t& r1, uint32_t& r2,
                                            uint32_t& r3, uint32_t addr) {
    asm volatile("ldmatrix.sync.aligned.m8n8.x4.shared.b16 {%0,%1,%2,%3}, [%4];"
                 : "=r"(r0), "=r"(r1), "=r"(r2), "=r"(r3) : "r"(addr));
}
__device__ __forceinline__ void mma_bf16(float* c, const uint32_t* a, uint32_t b0, uint32_t b1) {
    asm volatile("mma.sync.aligned.m16n8k16.row.col.f32.bf16.bf16.f32 "
                 "{%0,%1,%2,%3}, {%4,%5,%6,%7}, {%8,%9}, {%0,%1,%2,%3};"
                 : "+f"(c[0]), "+f"(c[1]), "+f"(c[2]), "+f"(c[3])
                 : "r"(a[0]), "r"(a[1]), "r"(a[2]), "r"(a[3]), "r"(b0), "r"(b1));
}
__device__ __forceinline__ uint32_t f16x2_pack(float lo, float hi) {
    uint32_t r;  // cvt.rn.f16x2.f32 d,a,b : high=a, low=b
    asm("cvt.rn.f16x2.f32 %0, %1, %2;" : "=r"(r) : "f"(hi), "f"(lo));
    return r;
}
__device__ __forceinline__ uint32_t ex2_f16x2(uint32_t x) {
    uint32_t y;
    asm("ex2.approx.f16x2 %0, %1;" : "=r"(y) : "r"(x));
    return y;
}
__device__ __forceinline__ uint32_t hadd2(uint32_t a, uint32_t b) {
    uint32_t r;
    asm("add.rn.f16x2 %0, %1, %2;" : "=r"(r) : "r"(a), "r"(b));
    return r;
}
// t in [0, NPAIR) -> (I,J), I<=J, row-major over upper triangle
__device__ __forceinline__ void decode_pair(int t, int& I, int& J) {
    int r = NPAIR - t;
    float nf = (sqrtf(8.0f * (float)r + 1.0f) - 1.0f) * 0.5f;
    int n = (int)ceilf(nf);
    while (n * (n + 1) / 2 < r) n++;
    while (n >= 1 && (n - 1) * n / 2 >= r) n--;
    I = NTILE - n;
    int S = NPAIR - n * (n + 1) / 2;
    J = I + (t - S);
}

// ============================================================
// Kernel A: normalize + pre-scale to bf16; zero rowsum/ctr
// ============================================================
__global__ void nt_norm_kernel(const float* __restrict__ h1,
                               const float* __restrict__ h2) {
    int gid = blockIdx.x * blockDim.x + threadIdx.x;
    if (gid < TWON) g_rowsum[gid] = 0.0f;
    if (gid == 0)   g_ctr = 0;

    int warp = gid >> 5;
    int lane = threadIdx.x & 31;
    if (warp >= N) return;

    float4 a = ((const float4*)(h1 + (size_t)warp * D))[lane];
    float4 b = ((const float4*)(h2 + (size_t)warp * D))[lane];

    float sa = a.x*a.x + a.y*a.y + a.z*a.z + a.w*a.w;
    float sb = b.x*b.x + b.y*b.y + b.z*b.z + b.w*b.w;
    float sd = a.x*b.x + a.y*b.y + a.z*b.z + a.w*b.w;
    #pragma unroll
    for (int o = 16; o; o >>= 1) {
        sa += __shfl_xor_sync(0xffffffffu, sa, o);
        sb += __shfl_xor_sync(0xffffffffu, sb, o);
        sd += __shfl_xor_sync(0xffffffffu, sd, o);
    }
    float ra = 1.0f / fmaxf(sqrtf(sa), 1e-12f);
    float rb = 1.0f / fmaxf(sqrtf(sb), 1e-12f);
    if (lane == 0) g_pos[warp] = sd * ra * rb;

    float fa = ra * SQRT_SCALE, fb = rb * SQRT_SCALE;
    union { __nv_bfloat162 b2[2]; uint2 u; } pa, pb;
    pa.b2[0] = __floats2bfloat162_rn(a.x*fa, a.y*fa);
    pa.b2[1] = __floats2bfloat162_rn(a.z*fa, a.w*fa);
    pb.b2[0] = __floats2bfloat162_rn(b.x*fb, b.y*fb);
    pb.b2[1] = __floats2bfloat162_rn(b.z*fb, b.w*fb);
    ((uint2*)(g_Hb + (size_t)warp * D))[lane]       = pa.u;
    ((uint2*)(g_Hb + (size_t)(warp + N) * D))[lane] = pb.u;
}

// ============================================================
// Kernel B: symmetric persistent GEMM, chunked for I-locality,
//   triple-buffered, pr-pipelined epilogue, A-fragment reuse.
// ============================================================
#define PADROW    136
#define ROWB      (PADROW * 2)           // 272B
#define T_BYTES   (128 * ROWB)           // 34816
#define BUF_BYTES (2 * T_BYTES)          // A + B
#define SMEM_SZ   (3 * BUF_BYTES)        // 208896
#define NT        256

__device__ __forceinline__ void cp_tileA(uint32_t buf, int I, int tid) {
    const __nv_bfloat16* src = g_Hb + (size_t)I * 128 * D;
    #pragma unroll
    for (int c = tid; c < 2048; c += NT) {
        int r = c >> 4, kc = c & 15;
        cp_async16(buf + r * ROWB + kc * 16, src + (size_t)r * D + kc * 8);
    }
}
__device__ __forceinline__ void cp_tileB(uint32_t buf, int J, int tid) {
    const __nv_bfloat16* src = g_Hb + (size_t)J * 128 * D;
    #pragma unroll
    for (int c = tid; c < 2048; c += NT) {
        int r = c >> 4, kc = c & 15;
        cp_async16(buf + T_BYTES + r * ROWB + kc * 16, src + (size_t)r * D + kc * 8);
    }
}

__global__ void __launch_bounds__(NT, 1) nt_gemm_sym() {
    extern __shared__ char smem[];
    __shared__ int s_c;
    uint32_t sb = smem_u32(smem);
    const int tid    = threadIdx.x;
    const int lane   = tid & 31;
    const int wid    = tid >> 5;
    const int warp_m = wid & 3;      // rows warp_m*32
    const int warp_n = wid >> 2;     // cols warp_n*64

    // ---- first chunk ----
    if (tid == 0) s_c = atomicAdd(&g_ctr, 1);
    __syncthreads();
    int cpos = s_c * CHUNK;
    int cend = cpos + CHUNK;
    if (cpos >= NPAIR) { cpos = NPAIR; cend = NPAIR; }

    int curT = (cpos < cend) ? cpos++ : NPAIR;
    int curI = 0, curJ = 0;
    if (curT < NPAIR) decode_pair(curT, curI, curJ);
    if (curT < NPAIR) { cp_tileA(sb, curI, tid); cp_tileB(sb, curJ, tid); }
    CP_COMMIT();

    int nxtT = (cpos < cend) ? cpos++ : NPAIR;
    int nxtI = 0, nxtJ = 0;
    if (nxtT < NPAIR) decode_pair(nxtT, nxtI, nxtJ);
    if (nxtT < NPAIR) {
        if (nxtI != curI) cp_tileA(sb + BUF_BYTES, nxtI, tid);
        cp_tileB(sb + BUF_BYTES, nxtJ, tid);
    }
    CP_COMMIT();

    int p = 0, prevI = -1;
    uint32_t afrag[8][2][4];

    while (curT < NPAIR) {
        // ---- schedule next-next tile (atomic before the sync) ----
        bool need = (cpos >= cend);
        if (need && tid == 0) s_c = atomicAdd(&g_ctr, 1);
        CP_WAIT1();           // cur's group complete
        __syncthreads();      // s_c visible; prefetch buffer's old readers done
        if (need) {
            cpos = s_c * CHUNK;
            if (cpos > NPAIR) cpos = NPAIR;
            cend = cpos + CHUNK;
            if (cend > NPAIR) cend = NPAIR;
        }
        int t2 = (cpos < cend) ? cpos++ : NPAIR;
        int I2 = 0, J2 = 0;
        if (t2 < NPAIR) {
            decode_pair(t2, I2, J2);
            int pb = p + 2; if (pb >= 3) pb -= 3;
            uint32_t pbuf = sb + pb * BUF_BYTES;
            if (I2 != nxtI) cp_tileA(pbuf, I2, tid);
            cp_tileB(pbuf, J2, tid);
        }
        CP_COMMIT();

        // ---- compute cur from buffer p ----
        uint32_t abuf = sb + p * BUF_BYTES;
        uint32_t bbuf = abuf + T_BYTES;

        if (curI != prevI) {
            uint32_t abase = abuf + (warp_m * 32 + (lane & 15)) * ROWB + (lane >> 4) * 16;
            #pragma unroll
            for (int kst = 0; kst < 8; ++kst)
                #pragma unroll
                for (int ma = 0; ma < 2; ++ma)
                    ldmatrix_x4(afrag[kst][ma][0], afrag[kst][ma][1],
                                afrag[kst][ma][2], afrag[kst][ma][3],
                                abase + ma * 16 * ROWB + kst * 32);
        }
        prevI = curI;

        const bool diag = (curI == curJ);
        uint32_t colacc[8];
        #pragma unroll
        for (int na = 0; na < 8; ++na) colacc[na] = 0;
        uint32_t rlo[2] = {0, 0}, rhi[2] = {0, 0};

        uint32_t bbase = bbuf + (warp_n * 64 + (lane & 15)) * ROWB + (lane >> 4) * 16;

        #pragma unroll
        for (int pr = 0; pr < 4; ++pr) {   // n-strip: cols pr*16..+15 of warp slice
            float acc[2][2][4];
            #pragma unroll
            for (int ma = 0; ma < 2; ++ma)
                #pragma unroll
                for (int nl = 0; nl < 2; ++nl)
                    #pragma unroll
                    for (int q = 0; q < 4; ++q) acc[ma][nl][q] = 0.f;

            #pragma unroll
            for (int kst = 0; kst < 8; ++kst) {
                uint32_t r0, r1, r2, r3;
                ldmatrix_x4(r0, r1, r2, r3, bbase + pr * 16 * ROWB + kst * 32);
                mma_bf16(acc[0][0], afrag[kst][0], r0, r2);
                mma_bf16(acc[0][1], afrag[kst][0], r1, r3);
                mma_bf16(acc[1][0], afrag[kst][1], r0, r2);
                mma_bf16(acc[1][1], afrag[kst][1], r1, r3);
            }
            // strip epilogue (overlaps next strip's MMA in-warp)
            #pragma unroll
            for (int ma = 0; ma < 2; ++ma)
                #pragma unroll
                for (int nl = 0; nl < 2; ++nl) {
                    uint32_t e01 = ex2_f16x2(f16x2_pack(acc[ma][nl][0], acc[ma][nl][1]));
                    uint32_t e23 = ex2_f16x2(f16x2_pack(acc[ma][nl][2], acc[ma][nl][3]));
                    rlo[ma] = hadd2(rlo[ma], e01);
                    rhi[ma] = hadd2(rhi[ma], e23);
                    colacc[pr * 2 + nl] = hadd2(colacc[pr * 2 + nl], hadd2(e01, e23));
                }
        }

        // ---- rowsum flush (f16x2 quad reduce, f32 atomics) ----
        #pragma unroll
        for (int ma = 0; ma < 2; ++ma) {
            uint32_t vlo = rlo[ma], vhi = rhi[ma];
            vlo = hadd2(vlo, __shfl_xor_sync(0xffffffffu, vlo, 1));
            vlo = hadd2(vlo, __shfl_xor_sync(0xffffffffu, vlo, 2));
            vhi = hadd2(vhi, __shfl_xor_sync(0xffffffffu, vhi, 1));
            vhi = hadd2(vhi, __shfl_xor_sync(0xffffffffu, vhi, 2));
            if ((lane & 3) == 0) {
                float2 glo = __half22float2(*(__half2*)&vlo);
                float2 ghi = __half22float2(*(__half2*)&vhi);
                int row = curI * 128 + warp_m * 32 + ma * 16 + (lane >> 2);
                atomicAdd(&g_rowsum[row],     glo.x + glo.y);
                atomicAdd(&g_rowsum[row + 8], ghi.x + ghi.y);
            }
        }
        // ---- colsum flush (symmetry) ----
        if (!diag) {
            #pragma unroll
            for (int na = 0; na < 8; ++na) {
                uint32_t v = colacc[na];
                v = hadd2(v, __shfl_xor_sync(0xffffffffu, v, 4));
                v = hadd2(v, __shfl_xor_sync(0xffffffffu, v, 8));
                v = hadd2(v, __shfl_xor_sync(0xffffffffu, v, 16));
                if (lane < 4) {
                    float2 cs = __half22float2(*(__half2*)&v);
                    int col = curJ * 128 + warp_n * 64 + na * 8 + lane * 2;
                    atomicAdd(&g_rowsum[col],     cs.x);
                    atomicAdd(&g_rowsum[col + 1], cs.y);
                }
            }
        }

        // ---- rotate pipeline ----
        curT = nxtT; curI = nxtI; curJ = nxtJ;
        nxtT = t2;   nxtI = I2;   nxtJ = J2;
        p = (p == 2) ? 0 : p + 1;
    }
}

// ============================================================
// Kernel C: loss = mean( log(rowsum - exp(2)) - 2*pos )
// ============================================================
__global__ void nt_loss_kernel(float* __restrict__ out) {
    __shared__ double sred[16];
    const int tid  = threadIdx.x;
    const int lane = tid & 31;
    const int wid  = tid >> 5;

    double s = 0.0;
    for (int i = tid; i < TWON; i += 512) {
        float denom = g_rowsum[i] - DIAG_EXP2;
        float term  = logf(denom) - 2.0f * g_pos[i & (N - 1)];
        s += (double)term;
    }
    #pragma unroll
    for (int o = 16; o; o >>= 1) s += __shfl_xor_sync(0xffffffffu, s, o);
    if (lane == 0) sred[wid] = s;
    __syncthreads();
    if (wid == 0) {
        double tt = (lane < 16) ? sred[lane] : 0.0;
        #pragma unroll
        for (int o = 8; o; o >>= 1) tt += __shfl_xor_sync(0xffffffffu, tt, o);
        if (lane == 0) out[0] = (float)(tt / (double)TWON);
    }
}

// ============================================================
extern "C" void kernel_launch(void* const* d_in, const int* in_sizes, int n_in,
                              void* d_out, int out_size) {
    const float* h1 = (const float*)d_in[0];
    const float* h2 = (const float*)d_in[1];
    float* out = (float*)d_out;

    nt_norm_kernel<<<1024, 256>>>(h1, h2);

    cudaFuncSetAttribute(nt_gemm_sym,
                         cudaFuncAttributeMaxDynamicSharedMemorySize, SMEM_SZ);
    nt_gemm_sym<<<148, NT, SMEM_SZ>>>();

    nt_loss_kernel<<<1, 512>>>(out);
}

// round 9
// speedup vs baseline: 3.4188x; 1.0134x over previous
#include <cuda_runtime.h>
#include <cuda_bf16.h>
#include <cuda_fp16.h>
#include <math.h>
#include <stdint.h>

#define N     8192
#define D     128
#define TWON  16384
#define NTILE 128
#define NPAIR 8256             // NTILE*(NTILE+1)/2
#define CHUNK 8

#define DIAG_EXP2  7.38905609893065f
#define SQRT_SCALE 1.6986436f  // sqrt(2/ln2): acc = log2(exp arg)

// -------- persistent device scratch --------
__device__ __nv_bfloat16 g_Hb[TWON * D];
__device__ float g_pos[N];
__device__ float g_rowsum[TWON];
__device__ int   g_ctr;

// ============================================================
// helpers
// ============================================================
__device__ __forceinline__ uint32_t smem_u32(const void* p) {
    uint32_t a;
    asm("{ .reg .u64 t; cvta.to.shared.u64 t, %1; cvt.u32.u64 %0, t; }" : "=r"(a) : "l"(p));
    return a;
}
__device__ __forceinline__ void cp_async16(uint32_t saddr, const void* gaddr) {
    asm volatile("cp.async.cg.shared.global [%0], [%1], 16;" :: "r"(saddr), "l"(gaddr) : "memory");
}
#define CP_COMMIT() asm volatile("cp.async.commit_group;" ::: "memory")
#define CP_WAIT1()  asm volatile("cp.async.wait_group 1;" ::: "memory")

__device__ __forceinline__ void ldmatrix_x4(uint32_t& r0, uint32_t& r1, uint32_t& r2,
                                            uint32_t& r3, uint32_t addr) {
    asm volatile("ldmatrix.sync.aligned.m8n8.x4.shared.b16 {%0,%1,%2,%3}, [%4];"
                 : "=r"(r0), "=r"(r1), "=r"(r2), "=r"(r3) : "r"(addr));
}
__device__ __forceinline__ void mma_bf16(float* c, const uint32_t* a, uint32_t b0, uint32_t b1) {
    asm volatile("mma.sync.aligned.m16n8k16.row.col.f32.bf16.bf16.f32 "
                 "{%0,%1,%2,%3}, {%4,%5,%6,%7}, {%8,%9}, {%0,%1,%2,%3};"
                 : "+f"(c[0]), "+f"(c[1]), "+f"(c[2]), "+f"(c[3])
                 : "r"(a[0]), "r"(a[1]), "r"(a[2]), "r"(a[3]), "r"(b0), "r"(b1));
}
__device__ __forceinline__ uint32_t f16x2_pack(float lo, float hi) {
    uint32_t r;  // cvt.rn.f16x2.f32 d,a,b : high=a, low=b
    asm("cvt.rn.f16x2.f32 %0, %1, %2;" : "=r"(r) : "f"(hi), "f"(lo));
    return r;
}
__device__ __forceinline__ uint32_t ex2_f16x2(uint32_t x) {
    uint32_t y;
    asm("ex2.approx.f16x2 %0, %1;" : "=r"(y) : "r"(x));
    return y;
}
__device__ __forceinline__ uint32_t hadd2(uint32_t a, uint32_t b) {
    uint32_t r;
    asm("add.rn.f16x2 %0, %1, %2;" : "=r"(r) : "r"(a), "r"(b));
    return r;
}
// t in [0, NPAIR) -> (I,J), I<=J, row-major over upper triangle
__device__ __forceinline__ void decode_pair(int t, int& I, int& J) {
    int r = NPAIR - t;
    float nf = (sqrtf(8.0f * (float)r + 1.0f) - 1.0f) * 0.5f;
    int n = (int)ceilf(nf);
    while (n * (n + 1) / 2 < r) n++;
    while (n >= 1 && (n - 1) * n / 2 >= r) n--;
    I = NTILE - n;
    int S = NPAIR - n * (n + 1) / 2;
    J = I + (t - S);
}

// ============================================================
// Kernel A: normalize + pre-scale to bf16; zero rowsum/ctr
// ============================================================
__global__ void nt_norm_kernel(const float* __restrict__ h1,
                               const float* __restrict__ h2) {
    int gid = blockIdx.x * blockDim.x + threadIdx.x;
    if (gid < TWON) g_rowsum[gid] = 0.0f;
    if (gid == 0)   g_ctr = 0;

    int warp = gid >> 5;
    int lane = threadIdx.x & 31;
    if (warp >= N) return;

    float4 a = ((const float4*)(h1 + (size_t)warp * D))[lane];
    float4 b = ((const float4*)(h2 + (size_t)warp * D))[lane];

    float sa = a.x*a.x + a.y*a.y + a.z*a.z + a.w*a.w;
    float sb = b.x*b.x + b.y*b.y + b.z*b.z + b.w*b.w;
    float sd = a.x*b.x + a.y*b.y + a.z*b.z + a.w*b.w;
    #pragma unroll
    for (int o = 16; o; o >>= 1) {
        sa += __shfl_xor_sync(0xffffffffu, sa, o);
        sb += __shfl_xor_sync(0xffffffffu, sb, o);
        sd += __shfl_xor_sync(0xffffffffu, sd, o);
    }
    float ra = 1.0f / fmaxf(sqrtf(sa), 1e-12f);
    float rb = 1.0f / fmaxf(sqrtf(sb), 1e-12f);
    if (lane == 0) g_pos[warp] = sd * ra * rb;

    float fa = ra * SQRT_SCALE, fb = rb * SQRT_SCALE;
    union { __nv_bfloat162 b2[2]; uint2 u; } pa, pb;
    pa.b2[0] = __floats2bfloat162_rn(a.x*fa, a.y*fa);
    pa.b2[1] = __floats2bfloat162_rn(a.z*fa, a.w*fa);
    pb.b2[0] = __floats2bfloat162_rn(b.x*fb, b.y*fb);
    pb.b2[1] = __floats2bfloat162_rn(b.z*fb, b.w*fb);
    ((uint2*)(g_Hb + (size_t)warp * D))[lane]       = pa.u;
    ((uint2*)(g_Hb + (size_t)(warp + N) * D))[lane] = pb.u;
}

// ============================================================
// Kernel B: symmetric persistent GEMM, chunked I-locality,
//   triple-buffered, LDSM-pipelined strips, deferred row flush.
// ============================================================
#define PADROW    136
#define ROWB      (PADROW * 2)           // 272B
#define T_BYTES   (128 * ROWB)           // 34816
#define BUF_BYTES (2 * T_BYTES)
#define SMEM_SZ   (3 * BUF_BYTES)        // 208896
#define NT        256

__device__ __forceinline__ void cp_tileA(uint32_t buf, int I, int tid) {
    const __nv_bfloat16* src = g_Hb + (size_t)I * 128 * D;
    #pragma unroll
    for (int c = tid; c < 2048; c += NT) {
        int r = c >> 4, kc = c & 15;
        cp_async16(buf + r * ROWB + kc * 16, src + (size_t)r * D + kc * 8);
    }
}
__device__ __forceinline__ void cp_tileB(uint32_t buf, int J, int tid) {
    const __nv_bfloat16* src = g_Hb + (size_t)J * 128 * D;
    #pragma unroll
    for (int c = tid; c < 2048; c += NT) {
        int r = c >> 4, kc = c & 15;
        cp_async16(buf + T_BYTES + r * ROWB + kc * 16, src + (size_t)r * D + kc * 8);
    }
}

__global__ void __launch_bounds__(NT, 1) nt_gemm_sym() {
    extern __shared__ char smem[];
    __shared__ int s_c;
    uint32_t sb = smem_u32(smem);
    const int tid    = threadIdx.x;
    const int lane   = tid & 31;
    const int wid    = tid >> 5;
    const int warp_m = wid & 3;
    const int warp_n = wid >> 2;

    // ---- first chunk ----
    if (tid == 0) s_c = atomicAdd(&g_ctr, 1);
    __syncthreads();
    int cpos = s_c * CHUNK;
    int cend = cpos + CHUNK;
    if (cpos >= NPAIR) { cpos = NPAIR; cend = NPAIR; }

    int curT = (cpos < cend) ? cpos++ : NPAIR;
    int curI = 0, curJ = 0;
    if (curT < NPAIR) decode_pair(curT, curI, curJ);
    if (curT < NPAIR) { cp_tileA(sb, curI, tid); cp_tileB(sb, curJ, tid); }
    CP_COMMIT();

    int nxtT = (cpos < cend) ? cpos++ : NPAIR;
    int nxtI = 0, nxtJ = 0;
    if (nxtT < NPAIR) decode_pair(nxtT, nxtI, nxtJ);
    if (nxtT < NPAIR) {
        if (nxtI != curI) cp_tileA(sb + BUF_BYTES, nxtI, tid);
        cp_tileB(sb + BUF_BYTES, nxtJ, tid);
    }
    CP_COMMIT();

    int p = 0, prevI = -1;
    uint32_t afrag[8][2][4];
    float rs[4] = {0.f, 0.f, 0.f, 0.f};   // deferred row sums (rows +0,+8,+16,+24)

    while (curT < NPAIR) {
        // ---- schedule next-next tile ----
        bool need = (cpos >= cend);
        if (need && tid == 0) s_c = atomicAdd(&g_ctr, 1);
        CP_WAIT1();
        __syncthreads();
        if (need) {
            cpos = s_c * CHUNK;
            if (cpos > NPAIR) cpos = NPAIR;
            cend = cpos + CHUNK;
            if (cend > NPAIR) cend = NPAIR;
        }
        int t2 = (cpos < cend) ? cpos++ : NPAIR;
        int I2 = 0, J2 = 0;
        if (t2 < NPAIR) {
            decode_pair(t2, I2, J2);
            int pb = p + 2; if (pb >= 3) pb -= 3;
            uint32_t pbuf = sb + pb * BUF_BYTES;
            if (I2 != nxtI) cp_tileA(pbuf, I2, tid);
            cp_tileB(pbuf, J2, tid);
        }
        CP_COMMIT();

        uint32_t abuf = sb + p * BUF_BYTES;
        uint32_t bbuf = abuf + T_BYTES;

        // ---- I changed: flush deferred row sums, reload A fragments ----
        if (curI != prevI) {
            if (prevI >= 0) {
                #pragma unroll
                for (int i = 0; i < 4; ++i) {
                    rs[i] += __shfl_xor_sync(0xffffffffu, rs[i], 1);
                    rs[i] += __shfl_xor_sync(0xffffffffu, rs[i], 2);
                }
                if ((lane & 3) == 0) {
                    int r8 = lane >> 2;
                    #pragma unroll
                    for (int i = 0; i < 4; ++i)
                        atomicAdd(&g_rowsum[prevI * 128 + warp_m * 32 + i * 8 + r8], rs[i]);
                }
                rs[0] = rs[1] = rs[2] = rs[3] = 0.f;
            }
            uint32_t abase = abuf + (warp_m * 32 + (lane & 15)) * ROWB + (lane >> 4) * 16;
            #pragma unroll
            for (int kst = 0; kst < 8; ++kst)
                #pragma unroll
                for (int ma = 0; ma < 2; ++ma)
                    ldmatrix_x4(afrag[kst][ma][0], afrag[kst][ma][1],
                                afrag[kst][ma][2], afrag[kst][ma][3],
                                abase + ma * 16 * ROWB + kst * 32);
        }
        prevI = curI;

        const bool diag = (curI == curJ);
        uint32_t colacc[8];
        #pragma unroll
        for (int na = 0; na < 8; ++na) colacc[na] = 0;
        uint32_t rlo[2] = {0, 0}, rhi[2] = {0, 0};

        uint32_t bbase = bbuf + (warp_n * 64 + (lane & 15)) * ROWB + (lane >> 4) * 16;

        #pragma unroll
        for (int pr = 0; pr < 4; ++pr) {
            float acc[2][2][4];
            #pragma unroll
            for (int ma = 0; ma < 2; ++ma)
                #pragma unroll
                for (int nl = 0; nl < 2; ++nl)
                    #pragma unroll
                    for (int q = 0; q < 4; ++q) acc[ma][nl][q] = 0.f;

            // LDSM double-buffer across kst
            uint32_t bq[2][4];
            ldmatrix_x4(bq[0][0], bq[0][1], bq[0][2], bq[0][3],
                        bbase + pr * 16 * ROWB);
            #pragma unroll
            for (int kst = 0; kst < 8; ++kst) {
                int cb = kst & 1, nb = cb ^ 1;
                if (kst < 7)
                    ldmatrix_x4(bq[nb][0], bq[nb][1], bq[nb][2], bq[nb][3],
                                bbase + pr * 16 * ROWB + (kst + 1) * 32);
                mma_bf16(acc[0][0], afrag[kst][0], bq[cb][0], bq[cb][2]);
                mma_bf16(acc[0][1], afrag[kst][0], bq[cb][1], bq[cb][3]);
                mma_bf16(acc[1][0], afrag[kst][1], bq[cb][0], bq[cb][2]);
                mma_bf16(acc[1][1], afrag[kst][1], bq[cb][1], bq[cb][3]);
            }
            #pragma unroll
            for (int ma = 0; ma < 2; ++ma)
                #pragma unroll
                for (int nl = 0; nl < 2; ++nl) {
                    uint32_t e01 = ex2_f16x2(f16x2_pack(acc[ma][nl][0], acc[ma][nl][1]));
                    uint32_t e23 = ex2_f16x2(f16x2_pack(acc[ma][nl][2], acc[ma][nl][3]));
                    rlo[ma] = hadd2(rlo[ma], e01);
                    rhi[ma] = hadd2(rhi[ma], e23);
                    colacc[pr * 2 + nl] = hadd2(colacc[pr * 2 + nl], hadd2(e01, e23));
                }
        }

        // fold this tile's f16x2 row partials into persistent f32 (no shfl/atomic)
        #pragma unroll
        for (int ma = 0; ma < 2; ++ma) {
            float2 glo = __half22float2(*(__half2*)&rlo[ma]);
            float2 ghi = __half22float2(*(__half2*)&rhi[ma]);
            rs[ma*2]     += glo.x + glo.y;
            rs[ma*2 + 1] += ghi.x + ghi.y;
        }

        // ---- colsum flush (per tile; symmetry) ----
        if (!diag) {
            #pragma unroll
            for (int na = 0; na < 8; ++na) {
                uint32_t v = colacc[na];
                v = hadd2(v, __shfl_xor_sync(0xffffffffu, v, 4));
                v = hadd2(v, __shfl_xor_sync(0xffffffffu, v, 8));
                v = hadd2(v, __shfl_xor_sync(0xffffffffu, v, 16));
                if (lane < 4) {
                    float2 cs = __half22float2(*(__half2*)&v);
                    int col = curJ * 128 + warp_n * 64 + na * 8 + lane * 2;
                    atomicAdd(&g_rowsum[col],     cs.x);
                    atomicAdd(&g_rowsum[col + 1], cs.y);
                }
            }
        }

        // ---- rotate ----
        curT = nxtT; curI = nxtI; curJ = nxtJ;
        nxtT = t2;   nxtI = I2;   nxtJ = J2;
        p = (p == 2) ? 0 : p + 1;
    }

    // ---- final deferred row flush ----
    if (prevI >= 0) {
        #pragma unroll
        for (int i = 0; i < 4; ++i) {
            rs[i] += __shfl_xor_sync(0xffffffffu, rs[i], 1);
            rs[i] += __shfl_xor_sync(0xffffffffu, rs[i], 2);
        }
        if ((lane & 3) == 0) {
            int r8 = lane >> 2;
            #pragma unroll
            for (int i = 0; i < 4; ++i)
                atomicAdd(&g_rowsum[prevI * 128 + warp_m * 32 + i * 8 + r8], rs[i]);
        }
    }
}

// ============================================================
// Kernel C: loss = mean( log(rowsum - exp(2)) - 2*pos )
// ============================================================
__global__ void nt_loss_kernel(float* __restrict__ out) {
    __shared__ double sred[32];
    const int tid  = threadIdx.x;   // 1024
    const int lane = tid & 31;
    const int wid  = tid >> 5;

    double s = 0.0;
    for (int i = tid; i < TWON; i += 1024) {
        float denom = g_rowsum[i] - DIAG_EXP2;
        float term  = logf(denom) - 2.0f * g_pos[i & (N - 1)];
        s += (double)term;
    }
    #pragma unroll
    for (int o = 16; o; o >>= 1) s += __shfl_xor_sync(0xffffffffu, s, o);
    if (lane == 0) sred[wid] = s;
    __syncthreads();
    if (wid == 0) {
        double tt = sred[lane];
        #pragma unroll
        for (int o = 16; o; o >>= 1) tt += __shfl_xor_sync(0xffffffffu, tt, o);
        if (lane == 0) out[0] = (float)(tt / (double)TWON);
    }
}

// ============================================================
extern "C" void kernel_launch(void* const* d_in, const int* in_sizes, int n_in,
                              void* d_out, int out_size) {
    const float* h1 = (const float*)d_in[0];
    const float* h2 = (const float*)d_in[1];
    float* out = (float*)d_out;

    nt_norm_kernel<<<1024, 256>>>(h1, h2);

    cudaFuncSetAttribute(nt_gemm_sym,
                         cudaFuncAttributeMaxDynamicSharedMemorySize, SMEM_SZ);
    nt_gemm_sym<<<148, NT, SMEM_SZ>>>();

    nt_loss_kernel<<<1, 1024>>>(out);
}